// round 14
// baseline (speedup 1.0000x reference)
#include <cuda_runtime.h>

// Fused bleed-correction, v5.1: v3 structure (cbrt inside the sweep, hidden by
// FFMA ILP) + per-channel templating + conv coefficients in __constant__ as
// FFMA constant-bank operands (no coefficient registers / LDGs) + occupancy 5.
// (v5 resubmission: nbj_of/kc_of now __host__ __device__ constexpr.)
//
// out[i] = src[i] - sum_{j in {i-1,i+1}} [ conv3x3(src[j], kA) + conv3x3(f_ij, kB) ]
//   f_ij = (src[j]^0.5 * src[i])^(2/3) = cbrt(src[j] * src[i]^2)
// conv = cross-correlation, SAME zero pad.
//
// Tile: one block = 512 (full width) x 8 rows of one (channel, image).
// Full-width tiles -> x halo is always the image border (zero) -> no x predication.
// smem offset-by-1 layout (logical col c at phys c+1) -> conv reads are one
// aligned LDS.128 + LDS.64 per row, conflict-free.

namespace {

constexpr int Ww   = 512;
constexpr int TH   = 8;
constexpr int SROWS = TH + 2;      // 10 rows (y halo)
constexpr int SW_   = 516;         // row stride: data phys [0..512], zero pad at 513
constexpr int NTHREADS = 256;

__constant__ float cker[108];      // 12 x 3 x 3, copied from d_in[1] each launch

// Neighbor / kernel-index tables (reference kidx order: off=-1 then off=+1).
__host__ __device__ constexpr int nbj_of(int ch, int s) {
    return ch == 0 ? 1 : ch == 1 ? (s == 0 ? 0 : 2)
         : ch == 2 ? (s == 0 ? 1 : 3) : 2;
}
__host__ __device__ constexpr int kc_of(int ch, int s) {
    return ch == 0 ? 0 : ch == 1 ? (s == 0 ? 2 : 4)
         : ch == 2 ? (s == 0 ? 6 : 8) : 10;
}

__device__ __forceinline__ float cbrt_nonneg(float x) {
    // x >= 0. lg2(0) = -inf -> ex2 -> 0, matches zero padding.
    return __powf(x, 0.3333333333333333f);
}

// Load one full-width tile (+y halo) into smem with offset-1 layout.
__device__ __forceinline__ void load_tile(float* __restrict__ dst,
                                          const float* __restrict__ gimg,
                                          int gy0, int r0, int c4, int lane) {
    #pragma unroll
    for (int r = r0; r < SROWS; r += 2) {
        const int gy = gy0 + r - 1;
        const bool inr = (unsigned)gy < (unsigned)Ww;
        float4 v = make_float4(0.f, 0.f, 0.f, 0.f);
        if (inr) v = __ldg((const float4*)(gimg + (size_t)gy * Ww) + c4);
        // shift right by one: phys slot 4*c4 gets logical col 4*c4 - 1
        float up = __shfl_up_sync(0xffffffffu, v.w, 1);
        if (lane == 0) {
            up = 0.f;                               // c4==0: logical -1 = 0
            if (c4 != 0 && inr) up = __ldg(gimg + (size_t)gy * Ww + 4 * c4 - 1);
        }
        float* row = dst + r * SW_;
        *(float4*)(row + 4 * c4) = make_float4(up, v.x, v.y, v.z);
        if (c4 == 127) row[512] = v.w;              // logical col 511
    }
}

template <int CH>
__global__ __launch_bounds__(NTHREADS, 5)
void bleed_kernel(const float* __restrict__ sources,
                  float* __restrict__ out)
{
    __shared__ __align__(16) float s_src[SROWS * SW_];
    __shared__ __align__(16) float s_nb [SROWS * SW_];

    const int bid = blockIdx.x;
    const int img = bid & 31;
    const int gy0 = (bid >> 5) * TH;    // 64 y-tiles

    const int tid  = threadIdx.x;
    const int lane = tid & 31;
    const int c4   = tid & 127;         // float4 column index (0..127)
    const int lx   = c4 * 4;
    const int r0   = tid >> 7;          // 0 or 1
    const int oyb  = r0 * 4;            // output row base within tile

    const size_t imgStride = (size_t)Ww * Ww;
    const float* srcBase = sources + ((size_t)CH * 32 + img) * imgStride;

    // zero the phys-col-513 pad (read by the sweep's far-halo LDS.64)
    if (tid < SROWS) {
        s_src[tid * SW_ + 513] = 0.f;
        s_nb [tid * SW_ + 513] = 0.f;
    }

    load_tile(s_src, srcBase, gy0, r0, c4, lane);

    float acc[4][4];
    #pragma unroll
    for (int o = 0; o < 4; o++)
        #pragma unroll
        for (int c = 0; c < 4; c++) acc[o][c] = 0.f;

    constexpr int NNB = (CH == 0 || CH == 3) ? 1 : 2;

    #pragma unroll
    for (int s = 0; s < NNB; s++) {
        const int J  = nbj_of(CH, s);   // literal after unroll
        const int KC = kc_of(CH, s);    // literal after unroll
        const float* nbBase = sources + ((size_t)J * 32 + img) * imgStride;

        load_tile(s_nb, nbBase, gy0, r0, c4, lane);
        __syncthreads();    // nb tile visible (covers s_src on first pass)

        // ---- fused sweep: acc += kA (x) nb + kB (x) cbrt(nb*src^2) ----
        // Coefficients are compile-time-indexed __constant__ -> FFMA constant-bank
        // operands: no coefficient registers, no LDGs.
        #pragma unroll
        for (int iy = 0; iy < 6; iy++) {
            const float* rn = s_nb  + (oyb + iy) * SW_ + lx;  // 16B aligned
            const float* rs = s_src + (oyb + iy) * SW_ + lx;
            float4 n0 = *(const float4*)rn;
            float2 n1 = *(const float2*)(rn + 4);
            float4 s0 = *(const float4*)rs;
            float2 s1 = *(const float2*)(rs + 4);
            float n[6]  = {n0.x, n0.y, n0.z, n0.w, n1.x, n1.y};
            float sv[6] = {s0.x, s0.y, s0.z, s0.w, s1.x, s1.y};
            float f[6];
            #pragma unroll
            for (int c = 0; c < 6; c++)
                f[c] = cbrt_nonneg(n[c] * sv[c] * sv[c]);

            #pragma unroll
            for (int o = 0; o < 4; o++) {
                const int kr = iy - o;              // kernel row index
                if (kr >= 0 && kr < 3) {
                    #pragma unroll
                    for (int c = 0; c < 4; c++) {
                        float a = acc[o][c];
                        a = fmaf(cker[KC * 9 + kr * 3 + 0],       n[c + 0], a);
                        a = fmaf(cker[KC * 9 + kr * 3 + 1],       n[c + 1], a);
                        a = fmaf(cker[KC * 9 + kr * 3 + 2],       n[c + 2], a);
                        a = fmaf(cker[(KC + 1) * 9 + kr * 3 + 0], f[c + 0], a);
                        a = fmaf(cker[(KC + 1) * 9 + kr * 3 + 1], f[c + 1], a);
                        a = fmaf(cker[(KC + 1) * 9 + kr * 3 + 2], f[c + 2], a);
                        acc[o][c] = a;
                    }
                }
            }
        }

        if (s + 1 < NNB) __syncthreads();   // before next neighbor overwrites s_nb
    }

    // ---- epilogue: out = src - bleed (512 % 8 == 0 -> always in range) ----
    float* outBase = out + ((size_t)CH * 32 + img) * imgStride;
    #pragma unroll
    for (int o = 0; o < 4; o++) {
        const float* row = s_src + (oyb + o + 1) * SW_ + lx;  // phys = logical+1
        float4 a = *(const float4*)row;      // logical lx-1..lx+2
        float2 b = *(const float2*)(row + 4);
        float4 r;
        r.x = a.y - acc[o][0];
        r.y = a.z - acc[o][1];
        r.z = a.w - acc[o][2];
        r.w = b.x - acc[o][3];
        const int gy = gy0 + oyb + o;
        *(float4*)(outBase + (size_t)gy * Ww + lx) = r;
    }
}

}  // namespace

extern "C" void kernel_launch(void* const* d_in, const int* in_sizes, int n_in,
                              void* d_out, int out_size) {
    (void)in_sizes; (void)n_in; (void)out_size;
    const float* sources = (const float*)d_in[0];   // (4,32,512,512,1) fp32
    const float* kernels = (const float*)d_in[1];   // (12,3,3) fp32
    float* out = (float*)d_out;                     // (4,32,512,512,1) fp32

    // Stage conv coefficients into __constant__ (D2D async copy: graph-capturable,
    // allocation-free). Ordered before the kernels on the same stream.
    cudaMemcpyToSymbolAsync(cker, kernels, 108 * sizeof(float), 0,
                            cudaMemcpyDeviceToDevice, 0);

    // One launch per channel: 32 images * 64 y-tiles = 2048 blocks each.
    // Heavy (2-neighbor) channels first.
    bleed_kernel<1><<<2048, NTHREADS>>>(sources, out);
    bleed_kernel<2><<<2048, NTHREADS>>>(sources, out);
    bleed_kernel<0><<<2048, NTHREADS>>>(sources, out);
    bleed_kernel<3><<<2048, NTHREADS>>>(sources, out);
}